// round 1
// baseline (speedup 1.0000x reference)
#include <cuda_runtime.h>
#include <math.h>

#define NROWS 32768
#define DDIM  512
#define KCB   8192
#define TOPK  3
#define EPSF  1e-12f

// ---------------- device scratch (no allocations allowed) ----------------
__device__ float g_winv[KCB];
__device__ float g_wsq[KCB];
__device__ float g_xinv[NROWS];
__device__ float g_xsq[NROWS];
__device__ float g_topd[NROWS * TOPK];
__device__ int   g_topi[NROWS * TOPK];
__device__ float g_rowsum[NROWS];

// ---------------- row-norm kernel: one warp per row ----------------
__global__ void rownorm_kernel(const float* __restrict__ v, int rows,
                               float* __restrict__ inv_out, float* __restrict__ sq_out) {
    int warp = (blockIdx.x * blockDim.x + threadIdx.x) >> 5;
    int lane = threadIdx.x & 31;
    if (warp >= rows) return;
    const float* row = v + (size_t)warp * DDIM;
    float s = 0.f;
    #pragma unroll 4
    for (int d = lane; d < DDIM; d += 32) { float t = row[d]; s = fmaf(t, t, s); }
    #pragma unroll
    for (int o = 16; o; o >>= 1) s += __shfl_xor_sync(0xffffffffu, s, o);
    if (lane == 0) {
        float n   = sqrtf(s);
        float inv = 1.0f / fmaxf(n, EPSF);
        inv_out[warp] = inv;
        sq_out[warp]  = s * inv * inv;   // sum(xn^2), ~1
    }
}

// ---------------- fused GEMM + top-3 ----------------
#define BM 64
#define BN 128
#define BK 16
#define ASTRIDE (BM + 4)   // 68: 16B-aligned float4 rows, at most 2-way store conflicts
#define BSTRIDE (BN + 4)   // 132

__device__ __forceinline__ void topk_insert(float (&d)[3], int (&ix)[3], float nd, int ni) {
    // jax top_k tie-break: on equal value, lower index wins
    if (nd < d[2] || (nd == d[2] && ni < ix[2])) {
        if (nd < d[1] || (nd == d[1] && ni < ix[1])) {
            d[2] = d[1]; ix[2] = ix[1];
            if (nd < d[0] || (nd == d[0] && ni < ix[0])) {
                d[1] = d[0]; ix[1] = ix[0];
                d[0] = nd;   ix[0] = ni;
            } else { d[1] = nd; ix[1] = ni; }
        } else { d[2] = nd; ix[2] = ni; }
    }
}

__global__ __launch_bounds__(256)
void gemm_topk_kernel(const float* __restrict__ x, const float* __restrict__ w) {
    __shared__ float As[BK][ASTRIDE];
    __shared__ float Bs[BK][BSTRIDE];
    __shared__ float wsqs[BN];
    __shared__ float cd[BM][16 * TOPK];
    __shared__ int   ci[BM][16 * TOPK];

    const int tid  = threadIdx.x;
    const int ty   = tid >> 4;   // 0..15 -> 4 rows each
    const int tx   = tid & 15;   // 0..15 -> 8 cols each
    const int row0 = blockIdx.x * BM;

    float xsq_r[4];
    #pragma unroll
    for (int i = 0; i < 4; i++) xsq_r[i] = g_xsq[row0 + ty * 4 + i];

    float td[4][3]; int ti[4][3];
    #pragma unroll
    for (int i = 0; i < 4; i++) {
        td[i][0] = td[i][1] = td[i][2] = INFINITY;
        ti[i][0] = ti[i][1] = ti[i][2] = 0x7fffffff;
    }

    for (int kt = 0; kt < KCB; kt += BN) {
        if (tid < BN) wsqs[tid] = g_wsq[kt + tid];

        float acc[4][8];
        #pragma unroll
        for (int i = 0; i < 4; i++)
            #pragma unroll
            for (int j = 0; j < 8; j++) acc[i][j] = 0.f;

        for (int dt = 0; dt < DDIM; dt += BK) {
            // A tile: 64 rows x 16 d  (256 float4, 1 per thread), normalize on load
            {
                int m  = tid >> 2;
                int d4 = (tid & 3) << 2;
                float4 v = *reinterpret_cast<const float4*>(&x[(size_t)(row0 + m) * DDIM + dt + d4]);
                float s = g_xinv[row0 + m];
                As[d4 + 0][m] = v.x * s; As[d4 + 1][m] = v.y * s;
                As[d4 + 2][m] = v.z * s; As[d4 + 3][m] = v.w * s;
            }
            // B tile: 128 rows x 16 d (512 float4, 2 per thread), normalize on load
            #pragma unroll
            for (int it = 0; it < 2; it++) {
                int l  = tid + it * 256;
                int m  = l >> 2;
                int d4 = (l & 3) << 2;
                float4 v = *reinterpret_cast<const float4*>(&w[(size_t)(kt + m) * DDIM + dt + d4]);
                float s = g_winv[kt + m];
                Bs[d4 + 0][m] = v.x * s; Bs[d4 + 1][m] = v.y * s;
                Bs[d4 + 2][m] = v.z * s; Bs[d4 + 3][m] = v.w * s;
            }
            __syncthreads();
            #pragma unroll
            for (int d = 0; d < BK; d++) {
                float4 a  = *reinterpret_cast<const float4*>(&As[d][ty * 4]);
                float4 b0 = *reinterpret_cast<const float4*>(&Bs[d][tx * 8]);
                float4 b1 = *reinterpret_cast<const float4*>(&Bs[d][tx * 8 + 4]);
                float av[4] = {a.x, a.y, a.z, a.w};
                float bv[8] = {b0.x, b0.y, b0.z, b0.w, b1.x, b1.y, b1.z, b1.w};
                #pragma unroll
                for (int i = 0; i < 4; i++)
                    #pragma unroll
                    for (int j = 0; j < 8; j++)
                        acc[i][j] = fmaf(av[i], bv[j], acc[i][j]);
            }
            __syncthreads();
        }

        // distances + per-thread running top-3
        #pragma unroll
        for (int i = 0; i < 4; i++) {
            #pragma unroll
            for (int j = 0; j < 8; j++) {
                float dist = xsq_r[i] + wsqs[tx * 8 + j] - 2.0f * acc[i][j];
                int col = kt + tx * 8 + j;
                topk_insert(td[i], ti[i], dist, col);
            }
        }
        __syncthreads();   // protect wsqs before next overwrite
    }

    // cross-thread reduce: 16 threads per row, 48 candidates
    #pragma unroll
    for (int i = 0; i < 4; i++)
        #pragma unroll
        for (int s = 0; s < 3; s++) {
            cd[ty * 4 + i][tx * 3 + s] = td[i][s];
            ci[ty * 4 + i][tx * 3 + s] = ti[i][s];
        }
    __syncthreads();

    if (tid < BM) {
        float bd[3] = {INFINITY, INFINITY, INFINITY};
        int   bi[3] = {0x7fffffff, 0x7fffffff, 0x7fffffff};
        for (int c = 0; c < 16 * TOPK; c++)
            topk_insert(bd, bi, cd[tid][c], ci[tid][c]);
        int r = row0 + tid;
        #pragma unroll
        for (int s = 0; s < 3; s++) {
            g_topd[r * 3 + s] = bd[s];
            g_topi[r * 3 + s] = bi[s];
        }
    }
}

// ---------------- epilogue: weights, gather, quantize, ST, per-row loss ----------------
__global__ void epilogue_kernel(const float* __restrict__ x, const float* __restrict__ emb,
                                float* __restrict__ out) {
    const int n = blockIdx.x;
    const int t = threadIdx.x;   // 128 threads
    __shared__ float ws[3];
    __shared__ int   is_[3];
    __shared__ float red[128];

    if (t == 0) {
        float d0 = g_topd[n * 3 + 0], d1 = g_topd[n * 3 + 1], d2 = g_topd[n * 3 + 2];
        int   i0 = g_topi[n * 3 + 0], i1 = g_topi[n * 3 + 1], i2 = g_topi[n * 3 + 2];
        float v0 = 1.0f / d0, v1 = 1.0f / d1, v2 = 1.0f / d2;
        float s = (v0 + v1) + v2;
        ws[0] = v0 / s; ws[1] = v1 / s; ws[2] = v2 / s;
        is_[0] = i0; is_[1] = i1; is_[2] = i2;
        float* idx_out = out + (size_t)NROWS * DDIM + 1;
        idx_out[n * 3 + 0] = (float)i0;
        idx_out[n * 3 + 1] = (float)i1;
        idx_out[n * 3 + 2] = (float)i2;
    }
    __syncthreads();

    const float w0 = ws[0], w1 = ws[1], w2 = ws[2];
    const float* e0 = emb + (size_t)is_[0] * DDIM;
    const float* e1 = emb + (size_t)is_[1] * DDIM;
    const float* e2 = emb + (size_t)is_[2] * DDIM;

    float local = 0.f;
    #pragma unroll 4
    for (int d = t; d < DDIM; d += 128) {
        float q  = fmaf(w2, e2[d], fmaf(w1, e1[d], w0 * e0[d]));
        float xv = x[(size_t)n * DDIM + d];
        float diff = q - xv;
        out[(size_t)n * DDIM + d] = xv + diff;   // straight-through value
        local = fmaf(diff, diff, local);
    }
    red[t] = local;
    __syncthreads();
    #pragma unroll
    for (int o = 64; o; o >>= 1) {
        if (t < o) red[t] += red[t + o];
        __syncthreads();
    }
    if (t == 0) g_rowsum[n] = red[0];
}

// ---------------- deterministic loss reduction ----------------
__global__ void loss_kernel(float* __restrict__ out) {
    __shared__ double red[256];
    int t = threadIdx.x;
    double s = 0.0;
    for (int i = t; i < NROWS; i += 256) s += (double)g_rowsum[i];
    red[t] = s;
    __syncthreads();
    #pragma unroll
    for (int o = 128; o; o >>= 1) {
        if (t < o) red[t] += red[t + o];
        __syncthreads();
    }
    if (t == 0) {
        double mean = red[0] / (double)((size_t)NROWS * DDIM);
        out[(size_t)NROWS * DDIM] = (float)(1.25 * mean);   // q_loss + 0.25*e_loss
    }
}

// ---------------- launch ----------------
extern "C" void kernel_launch(void* const* d_in, const int* in_sizes, int n_in,
                              void* d_out, int out_size) {
    const float* x   = (const float*)d_in[0];
    const float* emb = (const float*)d_in[1];
    float* out = (float*)d_out;

    float *p_winv, *p_wsq, *p_xinv, *p_xsq;
    cudaGetSymbolAddress((void**)&p_winv, g_winv);
    cudaGetSymbolAddress((void**)&p_wsq,  g_wsq);
    cudaGetSymbolAddress((void**)&p_xinv, g_xinv);
    cudaGetSymbolAddress((void**)&p_xsq,  g_xsq);

    // 8 warps per block
    rownorm_kernel<<<KCB / 8, 256>>>(emb, KCB, p_winv, p_wsq);
    rownorm_kernel<<<NROWS / 8, 256>>>(x, NROWS, p_xinv, p_xsq);
    gemm_topk_kernel<<<NROWS / BM, 256>>>(x, emb);
    epilogue_kernel<<<NROWS, 128>>>(x, emb, out);
    loss_kernel<<<1, 256>>>(out);
}

// round 4
// speedup vs baseline: 1.8611x; 1.8611x over previous
#include <cuda_runtime.h>
#include <math.h>
#include <stdint.h>

#define NROWS 32768
#define DDIM  512
#define KCB   8192
#define EPSF  1e-12f

#define BM 128
#define BN 256
#define BK 16
#define KSTF 20                    // smem row stride in floats (80B)
#define GEMM_THREADS 512
#define APIECE (128*KSTF)
#define BPIECE (256*KSTF)
#define STAGEF (APIECE + BPIECE)   // 7680 floats
#define SMEM_BYTES (2*STAGEF*4)    // 61440 bytes

// ---------------- device scratch ----------------
__device__ float g_xn[(size_t)NROWS*DDIM];
__device__ float g_wn[(size_t)KCB*DDIM];
__device__ float g_xsq[NROWS];
__device__ float g_wsq[KCB];
__device__ int   g_top6[NROWS*6];
__device__ float g_rowsum[NROWS];

// ---------------- compensated arithmetic helpers ----------------
__device__ __forceinline__ void twosum(float a, float b, float& s, float& e) {
    s = a + b;
    float bp = s - a;
    e = (a - (s - bp)) + (b - bp);
}
// accumulate product x*w into (s,c) exactly-ish (TwoProdFMA + TwoSum)
__device__ __forceinline__ void acc_prod(float x, float w, float& s, float& c) {
    float p = x * w;
    float pe = fmaf(x, w, -p);
    float t, e;
    twosum(s, p, t, e);
    s = t;
    c += e + pe;
}

// ---------------- prep: normalize, store xn + exact sum(xn^2) ----------------
__global__ void prep_kernel(const float* __restrict__ v, int rows,
                            float* __restrict__ vn, float* __restrict__ sq) {
    int warp = (blockIdx.x * blockDim.x + threadIdx.x) >> 5;
    int lane = threadIdx.x & 31;
    if (warp >= rows) return;
    const float* row = v + (size_t)warp * DDIM;
    float vals[16];
    float s = 0.f;
#pragma unroll
    for (int i = 0; i < 16; i++) { vals[i] = row[lane + 32*i]; s = fmaf(vals[i], vals[i], s); }
#pragma unroll
    for (int o = 16; o; o >>= 1) s += __shfl_xor_sync(0xffffffffu, s, o);
    float nrm = fmaxf(sqrtf(s), EPSF);
    // exact sum of xn^2 (compensated)
    float s2 = 0.f, c2 = 0.f;
#pragma unroll
    for (int i = 0; i < 16; i++) {
        float xn = vals[i] / nrm;
        vn[(size_t)warp * DDIM + lane + 32*i] = xn;
        acc_prod(xn, xn, s2, c2);
    }
#pragma unroll
    for (int o = 16; o; o >>= 1) {
        float os = __shfl_xor_sync(0xffffffffu, s2, o);
        float oc = __shfl_xor_sync(0xffffffffu, c2, o);
        float t, e;
        twosum(s2, os, t, e);
        s2 = t; c2 += oc + e;
    }
    if (lane == 0) sq[warp] = s2 + c2;
}

// ---------------- generic top-S insert (tie: lower index wins) ----------------
template<int S>
__device__ __forceinline__ void topk_insert(float (&d)[S], int (&ix)[S], float nd, int ni) {
#pragma unroll
    for (int s = S - 1; s >= 0; s--) {
        bool better = (nd < d[s]) || (nd == d[s] && ni < ix[s]);
        if (!better) {
#pragma unroll
            for (int t = S - 1; t > s + 1; t--) { d[t] = d[t-1]; ix[t] = ix[t-1]; }
            if (s + 1 < S) { d[s+1] = nd; ix[s+1] = ni; }
            return;
        }
    }
#pragma unroll
    for (int t = S - 1; t > 0; t--) { d[t] = d[t-1]; ix[t] = ix[t-1]; }
    d[0] = nd; ix[0] = ni;
}

// ---------------- helpers ----------------
__device__ __forceinline__ void cp16(void* s, const void* g) {
    unsigned sa = (unsigned)__cvta_generic_to_shared(s);
    asm volatile("cp.async.cg.shared.global [%0], [%1], 16;" :: "r"(sa), "l"(g));
}

__device__ __forceinline__ void tf32split(float v, uint32_t& h, uint32_t& l) {
    asm("cvt.rna.tf32.f32 %0, %1;" : "=r"(h) : "f"(v));
    float lf = v - __uint_as_float(h);
    asm("cvt.rna.tf32.f32 %0, %1;" : "=r"(l) : "f"(lf));
}

#define MMA_TF32(C, A, B) \
    asm volatile("mma.sync.aligned.m16n8k8.row.col.f32.tf32.tf32.f32 " \
                 "{%0,%1,%2,%3},{%4,%5,%6,%7},{%8,%9},{%0,%1,%2,%3};" \
                 : "+f"(C[0]), "+f"(C[1]), "+f"(C[2]), "+f"(C[3]) \
                 : "r"(A[0]), "r"(A[1]), "r"(A[2]), "r"(A[3]), "r"(B[0]), "r"(B[1]))

// ---------------- fused 3xTF32 GEMM + top-6 nomination ----------------
__global__ __launch_bounds__(GEMM_THREADS)
void gemm_topk_kernel() {
    extern __shared__ __align__(16) float sm[];
    __shared__ float wsqs[BN];

    const int tid  = threadIdx.x;
    const int warp = tid >> 5, lane = tid & 31;
    const int wm = warp >> 2, wn = warp & 3;     // 4x4 warp grid
    const int gI = lane >> 2, tig = lane & 3;
    const int row0 = blockIdx.x * BM;

    const int lrow = tid >> 2;
    const int lch  = (tid & 3) * 4;

    float xsq_r[4];
#pragma unroll
    for (int s = 0; s < 4; s++)
        xsq_r[s] = g_xsq[row0 + wm*32 + (s>>1)*16 + (s&1)*8 + gI];

    float td[4][3]; int ti[4][3];
#pragma unroll
    for (int s = 0; s < 4; s++) {
        td[s][0] = td[s][1] = td[s][2] = INFINITY;
        ti[s][0] = ti[s][1] = ti[s][2] = 0x7fffffff;
    }

    for (int kt = 0; kt < KCB; kt += BN) {
        if (tid < BN) wsqs[tid] = g_wsq[kt + tid];

        float acc[2][8][4];
#pragma unroll
        for (int mt = 0; mt < 2; mt++)
#pragma unroll
            for (int nt = 0; nt < 8; nt++)
#pragma unroll
                for (int j = 0; j < 4; j++) acc[mt][nt][j] = 0.f;

        {
            float* st = sm;
            cp16(st + lrow*KSTF + lch, &g_xn[(size_t)(row0+lrow)*DDIM + lch]);
#pragma unroll
            for (int it = 0; it < 2; it++) {
                int l = tid + it*512, br = l >> 2, bc = (l & 3) * 4;
                cp16(st + APIECE + br*KSTF + bc, &g_wn[(size_t)(kt+br)*DDIM + bc]);
            }
            asm volatile("cp.async.commit_group;");
        }

        for (int dt = 0; dt < DDIM/BK; dt++) {
            if (dt + 1 < DDIM/BK) {
                float* st = sm + ((dt+1)&1)*STAGEF;
                int doff = (dt+1)*BK;
                cp16(st + lrow*KSTF + lch, &g_xn[(size_t)(row0+lrow)*DDIM + doff + lch]);
#pragma unroll
                for (int it = 0; it < 2; it++) {
                    int l = tid + it*512, br = l >> 2, bc = (l & 3) * 4;
                    cp16(st + APIECE + br*KSTF + bc, &g_wn[(size_t)(kt+br)*DDIM + doff + bc]);
                }
                asm volatile("cp.async.commit_group;");
                asm volatile("cp.async.wait_group 1;");
            } else {
                asm volatile("cp.async.wait_group 0;");
            }
            __syncthreads();

            const float* As = sm + (dt&1)*STAGEF;
            const float* Bs = As + APIECE;

#pragma unroll
            for (int k8 = 0; k8 < 2; k8++) {
                const int kof = k8*8 + tig;
                uint32_t ah[2][4], al[2][4];
#pragma unroll
                for (int mt = 0; mt < 2; mt++) {
                    int r = wm*32 + mt*16 + gI;
                    float v0 = As[(r  )*KSTF + kof];
                    float v1 = As[(r+8)*KSTF + kof];
                    float v2 = As[(r  )*KSTF + kof + 4];
                    float v3 = As[(r+8)*KSTF + kof + 4];
                    tf32split(v0, ah[mt][0], al[mt][0]);
                    tf32split(v1, ah[mt][1], al[mt][1]);
                    tf32split(v2, ah[mt][2], al[mt][2]);
                    tf32split(v3, ah[mt][3], al[mt][3]);
                }
#pragma unroll
                for (int nt = 0; nt < 8; nt++) {
                    int nr = wn*64 + nt*8 + gI;
                    float w0 = Bs[nr*KSTF + kof];
                    float w1 = Bs[nr*KSTF + kof + 4];
                    uint32_t bh[2], bl[2];
                    tf32split(w0, bh[0], bl[0]);
                    tf32split(w1, bh[1], bl[1]);
#pragma unroll
                    for (int mt = 0; mt < 2; mt++) {
                        MMA_TF32(acc[mt][nt], ah[mt], bh);
                        MMA_TF32(acc[mt][nt], ah[mt], bl);
                        MMA_TF32(acc[mt][nt], al[mt], bh);
                    }
                }
            }
            __syncthreads();
        }

#pragma unroll
        for (int mt = 0; mt < 2; mt++)
#pragma unroll
            for (int nt = 0; nt < 8; nt++) {
                int colb = wn*64 + nt*8 + tig*2;
                float w0 = wsqs[colb], w1 = wsqs[colb+1];
                int gc = kt + colb;
                float d00 = xsq_r[mt*2]   + w0 - 2.f*acc[mt][nt][0];
                float d01 = xsq_r[mt*2]   + w1 - 2.f*acc[mt][nt][1];
                float d10 = xsq_r[mt*2+1] + w0 - 2.f*acc[mt][nt][2];
                float d11 = xsq_r[mt*2+1] + w1 - 2.f*acc[mt][nt][3];
                topk_insert<3>(td[mt*2],   ti[mt*2],   d00, gc);
                topk_insert<3>(td[mt*2],   ti[mt*2],   d01, gc+1);
                topk_insert<3>(td[mt*2+1], ti[mt*2+1], d10, gc);
                topk_insert<3>(td[mt*2+1], ti[mt*2+1], d11, gc+1);
            }
        __syncthreads();
    }

    // cross-thread reduce: 48 candidates -> top-6 nominations per row
    float* cd = sm;                          // [128][48]
    int*   ci = (int*)(sm + 128*48);         // [128][48]
#pragma unroll
    for (int s = 0; s < 4; s++) {
        int rl = wm*32 + (s>>1)*16 + (s&1)*8 + gI;
        int cs = (wn*4 + tig)*3;
#pragma unroll
        for (int j = 0; j < 3; j++) {
            cd[rl*48 + cs + j] = td[s][j];
            ci[rl*48 + cs + j] = ti[s][j];
        }
    }
    __syncthreads();

    if (tid < BM) {
        float bd[6]; int bi[6];
#pragma unroll
        for (int s = 0; s < 6; s++) { bd[s] = INFINITY; bi[s] = 0x7fffffff; }
        for (int c = 0; c < 48; c++)
            topk_insert<6>(bd, bi, cd[tid*48 + c], ci[tid*48 + c]);
        int r = row0 + tid;
#pragma unroll
        for (int s = 0; s < 6; s++) g_top6[r*6 + s] = bi[s];
    }
}

// ---------------- epilogue: EXACT refine (compensated fp32), weights, quantize, ST, loss ----------------
__global__ void epilogue_kernel(const float* __restrict__ x, const float* __restrict__ emb,
                                float* __restrict__ out) {
    const int n = blockIdx.x;
    const int t = threadIdx.x;   // 128 threads
    __shared__ int   cidx[6];
    __shared__ float part_s[6][128];
    __shared__ float part_c[6][128];
    __shared__ float dist6[6];
    __shared__ float ws[3];
    __shared__ int   sel[3];
    __shared__ float red[128];

    if (t < 6) cidx[t] = g_top6[n*6 + t];
    __syncthreads();

    // compensated fp32 dots of normalized vectors for 6 candidates (error ~2^-48)
    float ps[6] = {0,0,0,0,0,0}, pc[6] = {0,0,0,0,0,0};
    const float* xr = g_xn + (size_t)n * DDIM;
#pragma unroll 2
    for (int d = t; d < DDIM; d += 128) {
        float xv = xr[d];
#pragma unroll
        for (int c = 0; c < 6; c++)
            acc_prod(xv, g_wn[(size_t)cidx[c]*DDIM + d], ps[c], pc[c]);
    }
#pragma unroll
    for (int c = 0; c < 6; c++) { part_s[c][t] = ps[c]; part_c[c][t] = pc[c]; }
    __syncthreads();

    if (t < 6) {
        float s = 0.f, cc = 0.f;
        for (int i = 0; i < 128; i++) {
            float tt, e;
            twosum(s, part_s[t][i], tt, e);
            s = tt; cc += e + part_c[t][i];
        }
        float dot = s + cc;
        dist6[t] = g_xsq[n] + g_wsq[cidx[t]] - 2.f * dot;
    }
    __syncthreads();

    if (t == 0) {
        float bd[3] = {INFINITY, INFINITY, INFINITY};
        int   bs[3] = {0, 0, 0};
        bool  hv[3] = {false, false, false};
        for (int c = 0; c < 6; c++) {
            float nd = dist6[c]; int ni = cidx[c];
            if (!hv[2] || nd < bd[2] || (nd == bd[2] && ni < cidx[bs[2]])) {
                if (!hv[1] || nd < bd[1] || (nd == bd[1] && ni < cidx[bs[1]])) {
                    bd[2] = bd[1]; bs[2] = bs[1]; hv[2] = hv[1];
                    if (!hv[0] || nd < bd[0] || (nd == bd[0] && ni < cidx[bs[0]])) {
                        bd[1] = bd[0]; bs[1] = bs[0]; hv[1] = hv[0];
                        bd[0] = nd;   bs[0] = c;     hv[0] = true;
                    } else { bd[1] = nd; bs[1] = c; hv[1] = true; }
                } else { bd[2] = nd; bs[2] = c; hv[2] = true; }
            }
        }
        float v0 = 1.f/bd[0], v1 = 1.f/bd[1], v2 = 1.f/bd[2];
        float ssum = (v0 + v1) + v2;
        ws[0] = v0/ssum; ws[1] = v1/ssum; ws[2] = v2/ssum;
        sel[0] = cidx[bs[0]]; sel[1] = cidx[bs[1]]; sel[2] = cidx[bs[2]];
        float* idx_out = out + (size_t)NROWS*DDIM + 1;
        idx_out[n*3+0] = (float)sel[0];
        idx_out[n*3+1] = (float)sel[1];
        idx_out[n*3+2] = (float)sel[2];
    }
    __syncthreads();

    const float w0 = ws[0], w1 = ws[1], w2 = ws[2];
    const float* e0 = emb + (size_t)sel[0]*DDIM;
    const float* e1 = emb + (size_t)sel[1]*DDIM;
    const float* e2 = emb + (size_t)sel[2]*DDIM;

    float local = 0.f;
#pragma unroll 4
    for (int d = t; d < DDIM; d += 128) {
        float q  = fmaf(w2, e2[d], fmaf(w1, e1[d], w0*e0[d]));
        float xv = x[(size_t)n*DDIM + d];
        float diff = q - xv;
        out[(size_t)n*DDIM + d] = xv + diff;
        local = fmaf(diff, diff, local);
    }
    red[t] = local;
    __syncthreads();
#pragma unroll
    for (int o = 64; o; o >>= 1) {
        if (t < o) red[t] += red[t+o];
        __syncthreads();
    }
    if (t == 0) g_rowsum[n] = red[0];
}

// ---------------- deterministic loss reduction ----------------
__global__ void loss_kernel(float* __restrict__ out) {
    __shared__ double red[256];
    int t = threadIdx.x;
    double s = 0.0;
    for (int i = t; i < NROWS; i += 256) s += (double)g_rowsum[i];
    red[t] = s;
    __syncthreads();
#pragma unroll
    for (int o = 128; o; o >>= 1) {
        if (t < o) red[t] += red[t+o];
        __syncthreads();
    }
    if (t == 0) {
        double mean = red[0] / (double)((size_t)NROWS*DDIM);
        out[(size_t)NROWS*DDIM] = (float)(1.25 * mean);
    }
}

// ---------------- launch ----------------
extern "C" void kernel_launch(void* const* d_in, const int* in_sizes, int n_in,
                              void* d_out, int out_size) {
    const float* x   = (const float*)d_in[0];
    const float* emb = (const float*)d_in[1];
    float* out = (float*)d_out;

    float *p_xn, *p_wn, *p_xsq, *p_wsq;
    cudaGetSymbolAddress((void**)&p_xn,  g_xn);
    cudaGetSymbolAddress((void**)&p_wn,  g_wn);
    cudaGetSymbolAddress((void**)&p_xsq, g_xsq);
    cudaGetSymbolAddress((void**)&p_wsq, g_wsq);

    cudaFuncSetAttribute(gemm_topk_kernel,
                         cudaFuncAttributeMaxDynamicSharedMemorySize, SMEM_BYTES);

    prep_kernel<<<KCB/8,   256>>>(emb, KCB,   p_wn, p_wsq);
    prep_kernel<<<NROWS/8, 256>>>(x,   NROWS, p_xn, p_xsq);
    gemm_topk_kernel<<<NROWS/BM, GEMM_THREADS, SMEM_BYTES>>>();
    epilogue_kernel<<<NROWS, 128>>>(x, emb, out);
    loss_kernel<<<1, 256>>>(out);
}

// round 5
// speedup vs baseline: 2.7606x; 1.4833x over previous
#include <cuda_runtime.h>
#include <cuda_bf16.h>
#include <math.h>
#include <stdint.h>

#define NROWS 32768
#define DDIM  512
#define KCB   8192
#define EPSF  1e-12f

#define BM 128
#define BN 128
#define BK 32
#define KST 40                    // smem row stride in bf16 (80B -> conflict-free frag loads)
#define GEMM_THREADS 512
#define PIECE (128*KST)           // elems per piece (A/B hi/lo)
#define STAGE (4*PIECE)           // elems per stage
#define SMEM_BYTES (2*STAGE*2)    // 81920 bytes

// ---------------- device scratch ----------------
__device__ __align__(128) __nv_bfloat16 g_xh[(size_t)NROWS*DDIM];
__device__ __align__(128) __nv_bfloat16 g_xl[(size_t)NROWS*DDIM];
__device__ __align__(128) __nv_bfloat16 g_wh[(size_t)KCB*DDIM];
__device__ __align__(128) __nv_bfloat16 g_wl[(size_t)KCB*DDIM];
__device__ __align__(128) float g_xn[(size_t)NROWS*DDIM];
__device__ __align__(128) float g_wn[(size_t)KCB*DDIM];
__device__ float g_xsq[NROWS];
__device__ float g_wsq[KCB];
__device__ int   g_top8[NROWS*8];
__device__ float g_rowsum[NROWS];

// ---------------- compensated arithmetic ----------------
__device__ __forceinline__ void twosum(float a, float b, float& s, float& e) {
    s = a + b;
    float bp = s - a;
    e = (a - (s - bp)) + (b - bp);
}
__device__ __forceinline__ void acc_prod(float x, float w, float& s, float& c) {
    float p = x * w;
    float pe = fmaf(x, w, -p);
    float t, e;
    twosum(s, p, t, e);
    s = t;
    c += e + pe;
}

// ---------------- prep: normalize -> fp32 xn, bf16 hi/lo, exact xsq ----------------
__global__ void prep_kernel(const float* __restrict__ v, int rows,
                            float* __restrict__ vn,
                            __nv_bfloat16* __restrict__ hi,
                            __nv_bfloat16* __restrict__ lo,
                            float* __restrict__ sq) {
    int warp = (blockIdx.x * blockDim.x + threadIdx.x) >> 5;
    int lane = threadIdx.x & 31;
    if (warp >= rows) return;
    const float* row = v + (size_t)warp * DDIM;
    float vals[16];
    float s = 0.f;
#pragma unroll
    for (int i = 0; i < 16; i++) { vals[i] = row[lane + 32*i]; s = fmaf(vals[i], vals[i], s); }
#pragma unroll
    for (int o = 16; o; o >>= 1) s += __shfl_xor_sync(0xffffffffu, s, o);
    float nrm = fmaxf(sqrtf(s), EPSF);
    float s2 = 0.f, c2 = 0.f;
#pragma unroll
    for (int i = 0; i < 16; i++) {
        float xn = vals[i] / nrm;
        size_t off = (size_t)warp * DDIM + lane + 32*i;
        vn[off] = xn;
        __nv_bfloat16 h = __float2bfloat16(xn);
        __nv_bfloat16 l = __float2bfloat16(xn - __bfloat162float(h));
        hi[off] = h;
        lo[off] = l;
        acc_prod(xn, xn, s2, c2);
    }
#pragma unroll
    for (int o = 16; o; o >>= 1) {
        float os = __shfl_xor_sync(0xffffffffu, s2, o);
        float oc = __shfl_xor_sync(0xffffffffu, c2, o);
        float t, e;
        twosum(s2, os, t, e);
        s2 = t; c2 += oc + e;
    }
    if (lane == 0) sq[warp] = s2 + c2;
}

// ---------------- generic top-S insert (tie: lower index wins) ----------------
template<int S>
__device__ __forceinline__ void topk_insert(float (&d)[S], int (&ix)[S], float nd, int ni) {
#pragma unroll
    for (int s = S - 1; s >= 0; s--) {
        bool better = (nd < d[s]) || (nd == d[s] && ni < ix[s]);
        if (!better) {
#pragma unroll
            for (int t = S - 1; t > s + 1; t--) { d[t] = d[t-1]; ix[t] = ix[t-1]; }
            if (s + 1 < S) { d[s+1] = nd; ix[s+1] = ni; }
            return;
        }
    }
#pragma unroll
    for (int t = S - 1; t > 0; t--) { d[t] = d[t-1]; ix[t] = ix[t-1]; }
    d[0] = nd; ix[0] = ni;
}

// ---------------- helpers ----------------
__device__ __forceinline__ void cp16(void* s, const void* g) {
    unsigned sa = (unsigned)__cvta_generic_to_shared(s);
    asm volatile("cp.async.cg.shared.global [%0], [%1], 16;" :: "r"(sa), "l"(g));
}

#define MMA_BF16(C, A, B) \
    asm volatile("mma.sync.aligned.m16n8k16.row.col.f32.bf16.bf16.f32 " \
                 "{%0,%1,%2,%3},{%4,%5,%6,%7},{%8,%9},{%0,%1,%2,%3};" \
                 : "+f"(C[0]), "+f"(C[1]), "+f"(C[2]), "+f"(C[3]) \
                 : "r"(A[0]), "r"(A[1]), "r"(A[2]), "r"(A[3]), "r"(B[0]), "r"(B[1]))

// ---------------- fused bf16-3pass GEMM + top-8 nomination ----------------
__global__ __launch_bounds__(GEMM_THREADS, 1)
void gemm_topk_kernel() {
    extern __shared__ __align__(16) char dynsm[];
    __nv_bfloat16* sm = (__nv_bfloat16*)dynsm;
    __shared__ float wsqs[BN];

    const int tid  = threadIdx.x;
    const int warp = tid >> 5, lane = tid & 31;
    const int wm = warp >> 2, wn = warp & 3;       // 4x4 warp grid
    const int gI = lane >> 2, tig = lane & 3;
    const int row0 = blockIdx.x * BM;

    const int lrow = tid >> 2;
    const int lch  = (tid & 3) * 8;   // bf16 element offset within 32-wide k slab

    float xsq_r[4];
#pragma unroll
    for (int s = 0; s < 4; s++)
        xsq_r[s] = g_xsq[row0 + wm*32 + (s>>1)*16 + gI + (s&1)*8];

    float td[4][3]; int ti[4][3];
#pragma unroll
    for (int s = 0; s < 4; s++) {
        td[s][0] = td[s][1] = td[s][2] = INFINITY;
        ti[s][0] = ti[s][1] = ti[s][2] = 0x7fffffff;
    }

    for (int kt = 0; kt < KCB; kt += BN) {
        if (tid < BN) wsqs[tid] = g_wsq[kt + tid];

        float acc[2][4][4];
#pragma unroll
        for (int mt = 0; mt < 2; mt++)
#pragma unroll
            for (int nt = 0; nt < 4; nt++)
#pragma unroll
                for (int j = 0; j < 4; j++) acc[mt][nt][j] = 0.f;

        {
            __nv_bfloat16* st = sm;
            cp16(st +           lrow*KST + lch, &g_xh[(size_t)(row0+lrow)*DDIM + lch]);
            cp16(st + PIECE   + lrow*KST + lch, &g_xl[(size_t)(row0+lrow)*DDIM + lch]);
            cp16(st + 2*PIECE + lrow*KST + lch, &g_wh[(size_t)(kt  +lrow)*DDIM + lch]);
            cp16(st + 3*PIECE + lrow*KST + lch, &g_wl[(size_t)(kt  +lrow)*DDIM + lch]);
            asm volatile("cp.async.commit_group;");
        }

        for (int dt = 0; dt < DDIM/BK; dt++) {
            if (dt + 1 < DDIM/BK) {
                __nv_bfloat16* st = sm + ((dt+1)&1)*STAGE;
                int doff = (dt+1)*BK + lch;
                cp16(st +           lrow*KST + lch, &g_xh[(size_t)(row0+lrow)*DDIM + doff]);
                cp16(st + PIECE   + lrow*KST + lch, &g_xl[(size_t)(row0+lrow)*DDIM + doff]);
                cp16(st + 2*PIECE + lrow*KST + lch, &g_wh[(size_t)(kt  +lrow)*DDIM + doff]);
                cp16(st + 3*PIECE + lrow*KST + lch, &g_wl[(size_t)(kt  +lrow)*DDIM + doff]);
                asm volatile("cp.async.commit_group;");
                asm volatile("cp.async.wait_group 1;");
            } else {
                asm volatile("cp.async.wait_group 0;");
            }
            __syncthreads();

            const __nv_bfloat16* Ah = sm + (dt&1)*STAGE;
            const __nv_bfloat16* Al = Ah + PIECE;
            const __nv_bfloat16* Bh = Ah + 2*PIECE;
            const __nv_bfloat16* Bl = Ah + 3*PIECE;

#pragma unroll
            for (int k16 = 0; k16 < 2; k16++) {
                const int kof = k16*16 + tig*2;
                uint32_t ah[2][4], al[2][4];
#pragma unroll
                for (int mt = 0; mt < 2; mt++) {
                    int r = wm*32 + mt*16 + gI;
                    ah[mt][0] = *(const uint32_t*)(Ah + (r  )*KST + kof);
                    ah[mt][1] = *(const uint32_t*)(Ah + (r+8)*KST + kof);
                    ah[mt][2] = *(const uint32_t*)(Ah + (r  )*KST + kof + 8);
                    ah[mt][3] = *(const uint32_t*)(Ah + (r+8)*KST + kof + 8);
                    al[mt][0] = *(const uint32_t*)(Al + (r  )*KST + kof);
                    al[mt][1] = *(const uint32_t*)(Al + (r+8)*KST + kof);
                    al[mt][2] = *(const uint32_t*)(Al + (r  )*KST + kof + 8);
                    al[mt][3] = *(const uint32_t*)(Al + (r+8)*KST + kof + 8);
                }
#pragma unroll
                for (int nt = 0; nt < 4; nt++) {
                    int nr = wn*32 + nt*8 + gI;
                    uint32_t bh[2], bl[2];
                    bh[0] = *(const uint32_t*)(Bh + nr*KST + kof);
                    bh[1] = *(const uint32_t*)(Bh + nr*KST + kof + 8);
                    bl[0] = *(const uint32_t*)(Bl + nr*KST + kof);
                    bl[1] = *(const uint32_t*)(Bl + nr*KST + kof + 8);
#pragma unroll
                    for (int mt = 0; mt < 2; mt++) {
                        MMA_BF16(acc[mt][nt], ah[mt], bh);
                        MMA_BF16(acc[mt][nt], ah[mt], bl);
                        MMA_BF16(acc[mt][nt], al[mt], bh);
                    }
                }
            }
            __syncthreads();
        }

        // distances + per-thread running top-3
#pragma unroll
        for (int mt = 0; mt < 2; mt++)
#pragma unroll
            for (int nt = 0; nt < 4; nt++) {
                int colb = wn*32 + nt*8 + tig*2;
                float w0 = wsqs[colb], w1 = wsqs[colb+1];
                int gc = kt + colb;
                float d00 = xsq_r[mt*2]   + w0 - 2.f*acc[mt][nt][0];
                float d01 = xsq_r[mt*2]   + w1 - 2.f*acc[mt][nt][1];
                float d10 = xsq_r[mt*2+1] + w0 - 2.f*acc[mt][nt][2];
                float d11 = xsq_r[mt*2+1] + w1 - 2.f*acc[mt][nt][3];
                topk_insert<3>(td[mt*2],   ti[mt*2],   d00, gc);
                topk_insert<3>(td[mt*2],   ti[mt*2],   d01, gc+1);
                topk_insert<3>(td[mt*2+1], ti[mt*2+1], d10, gc);
                topk_insert<3>(td[mt*2+1], ti[mt*2+1], d11, gc+1);
            }
        __syncthreads();
    }

    // cross-thread reduce: 16 owner threads per row, 48 candidates -> top-8
    float* cd = (float*)dynsm;                          // [BM][48]
    int*   ci = (int*)(dynsm + BM*48*sizeof(float));    // [BM][48]
#pragma unroll
    for (int s = 0; s < 4; s++) {
        int rl = wm*32 + (s>>1)*16 + gI + (s&1)*8;
        int cs = (wn*4 + tig)*3;
#pragma unroll
        for (int j = 0; j < 3; j++) {
            cd[rl*48 + cs + j] = td[s][j];
            ci[rl*48 + cs + j] = ti[s][j];
        }
    }
    __syncthreads();

    if (tid < BM) {
        float bd[8]; int bi[8];
#pragma unroll
        for (int s = 0; s < 8; s++) { bd[s] = INFINITY; bi[s] = 0x7fffffff; }
        for (int c = 0; c < 48; c++)
            topk_insert<8>(bd, bi, cd[tid*48 + c], ci[tid*48 + c]);
        int r = row0 + tid;
#pragma unroll
        for (int s = 0; s < 8; s++) g_top8[r*8 + s] = bi[s];
    }
}

// ---------------- epilogue: exact refine (warp per candidate), weights, quantize, loss ----------------
__global__ __launch_bounds__(256)
void epilogue_kernel(const float* __restrict__ x, const float* __restrict__ emb,
                     float* __restrict__ out) {
    const int n = blockIdx.x;
    const int t = threadIdx.x;     // 256 threads
    const int w = t >> 5, lane = t & 31;
    __shared__ int   cidx[8];
    __shared__ float dist8[8];
    __shared__ float ws[3];
    __shared__ int   sel[3];
    __shared__ float red[256];

    if (t < 8) cidx[t] = g_top8[n*8 + t];
    __syncthreads();

    // warp w: compensated-exact dot(xn, wn[cidx[w]])
    {
        const float* xr = g_xn + (size_t)n * DDIM;
        const float* wr = g_wn + (size_t)cidx[w] * DDIM;
        float s = 0.f, c = 0.f;
#pragma unroll
        for (int i = 0; i < 16; i++)
            acc_prod(xr[lane + 32*i], wr[lane + 32*i], s, c);
#pragma unroll
        for (int o = 16; o; o >>= 1) {
            float os = __shfl_xor_sync(0xffffffffu, s, o);
            float oc = __shfl_xor_sync(0xffffffffu, c, o);
            float tt, e;
            twosum(s, os, tt, e);
            s = tt; c += oc + e;
        }
        if (lane == 0)
            dist8[w] = g_xsq[n] + g_wsq[cidx[w]] - 2.f * (s + c);
    }
    __syncthreads();

    if (t == 0) {
        float bd[3] = {INFINITY, INFINITY, INFINITY};
        int   bs[3] = {0, 0, 0};
        bool  hv[3] = {false, false, false};
        for (int c = 0; c < 8; c++) {
            float nd = dist8[c]; int ni = cidx[c];
            if (!hv[2] || nd < bd[2] || (nd == bd[2] && ni < cidx[bs[2]])) {
                if (!hv[1] || nd < bd[1] || (nd == bd[1] && ni < cidx[bs[1]])) {
                    bd[2] = bd[1]; bs[2] = bs[1]; hv[2] = hv[1];
                    if (!hv[0] || nd < bd[0] || (nd == bd[0] && ni < cidx[bs[0]])) {
                        bd[1] = bd[0]; bs[1] = bs[0]; hv[1] = hv[0];
                        bd[0] = nd;   bs[0] = c;     hv[0] = true;
                    } else { bd[1] = nd; bs[1] = c; hv[1] = true; }
                } else { bd[2] = nd; bs[2] = c; hv[2] = true; }
            }
        }
        float v0 = 1.f/bd[0], v1 = 1.f/bd[1], v2 = 1.f/bd[2];
        float ssum = (v0 + v1) + v2;
        ws[0] = v0/ssum; ws[1] = v1/ssum; ws[2] = v2/ssum;
        sel[0] = cidx[bs[0]]; sel[1] = cidx[bs[1]]; sel[2] = cidx[bs[2]];
        float* idx_out = out + (size_t)NROWS*DDIM + 1;
        idx_out[n*3+0] = (float)sel[0];
        idx_out[n*3+1] = (float)sel[1];
        idx_out[n*3+2] = (float)sel[2];
    }
    __syncthreads();

    const float w0 = ws[0], w1 = ws[1], w2 = ws[2];
    const float* e0 = emb + (size_t)sel[0]*DDIM;
    const float* e1 = emb + (size_t)sel[1]*DDIM;
    const float* e2 = emb + (size_t)sel[2]*DDIM;

    float local = 0.f;
#pragma unroll
    for (int d = t; d < DDIM; d += 256) {
        float q  = fmaf(w2, e2[d], fmaf(w1, e1[d], w0*e0[d]));
        float xv = x[(size_t)n*DDIM + d];
        float diff = q - xv;
        out[(size_t)n*DDIM + d] = xv + diff;
        local = fmaf(diff, diff, local);
    }
    red[t] = local;
    __syncthreads();
#pragma unroll
    for (int o = 128; o; o >>= 1) {
        if (t < o) red[t] += red[t+o];
        __syncthreads();
    }
    if (t == 0) g_rowsum[n] = red[0];
}

// ---------------- deterministic loss reduction ----------------
__global__ void loss_kernel(float* __restrict__ out) {
    __shared__ double red[256];
    int t = threadIdx.x;
    double s = 0.0;
    for (int i = t; i < NROWS; i += 256) s += (double)g_rowsum[i];
    red[t] = s;
    __syncthreads();
#pragma unroll
    for (int o = 128; o; o >>= 1) {
        if (t < o) red[t] += red[t+o];
        __syncthreads();
    }
    if (t == 0) {
        double mean = red[0] / (double)((size_t)NROWS*DDIM);
        out[(size_t)NROWS*DDIM] = (float)(1.25 * mean);
    }
}

// ---------------- launch ----------------
extern "C" void kernel_launch(void* const* d_in, const int* in_sizes, int n_in,
                              void* d_out, int out_size) {
    const float* x   = (const float*)d_in[0];
    const float* emb = (const float*)d_in[1];
    float* out = (float*)d_out;

    __nv_bfloat16 *p_xh, *p_xl, *p_wh, *p_wl;
    float *p_xn, *p_wn, *p_xsq, *p_wsq;
    cudaGetSymbolAddress((void**)&p_xh,  g_xh);
    cudaGetSymbolAddress((void**)&p_xl,  g_xl);
    cudaGetSymbolAddress((void**)&p_wh,  g_wh);
    cudaGetSymbolAddress((void**)&p_wl,  g_wl);
    cudaGetSymbolAddress((void**)&p_xn,  g_xn);
    cudaGetSymbolAddress((void**)&p_wn,  g_wn);
    cudaGetSymbolAddress((void**)&p_xsq, g_xsq);
    cudaGetSymbolAddress((void**)&p_wsq, g_wsq);

    cudaFuncSetAttribute(gemm_topk_kernel,
                         cudaFuncAttributeMaxDynamicSharedMemorySize, SMEM_BYTES);

    prep_kernel<<<KCB/8,   256>>>(emb, KCB,   p_wn, p_wh, p_wl, p_wsq);
    prep_kernel<<<NROWS/8, 256>>>(x,   NROWS, p_xn, p_xh, p_xl, p_xsq);
    gemm_topk_kernel<<<NROWS/BM, GEMM_THREADS, SMEM_BYTES>>>();
    epilogue_kernel<<<NROWS, 256>>>(x, emb, out);
    loss_kernel<<<1, 256>>>(out);
}

// round 7
// speedup vs baseline: 5.2839x; 1.9141x over previous
#include <cuda_runtime.h>
#include <cuda_bf16.h>
#include <math.h>
#include <stdint.h>

#define NROWS 32768
#define DDIM  512
#define KCB   8192
#define EPSF  1e-12f

#define BM 128
#define BN 128
#define BK 32
#define KST 40                    // smem row stride in bf16 (80B -> conflict-free 8-row groups)
#define GEMM_THREADS 512
#define PIECE (128*KST)           // elems per piece (A or B)
#define STAGE (2*PIECE)           // elems per stage (A+B)
#define SMEM_BYTES 49280          // max(2*STAGE*2 = 40960, reduce scratch 49152) + pad

// ---------------- device scratch ----------------
__device__ __align__(128) __nv_bfloat16 g_xh[(size_t)NROWS*DDIM];
__device__ __align__(128) __nv_bfloat16 g_wh[(size_t)KCB*DDIM];
__device__ __align__(128) float g_xn[(size_t)NROWS*DDIM];
__device__ __align__(128) float g_wn[(size_t)KCB*DDIM];
__device__ float g_xsq[NROWS];
__device__ float g_wsq[KCB];
__device__ int   g_top8[NROWS*8];
__device__ float g_rowsum[NROWS];

// ---------------- compensated arithmetic ----------------
__device__ __forceinline__ void twosum(float a, float b, float& s, float& e) {
    s = a + b;
    float bp = s - a;
    e = (a - (s - bp)) + (b - bp);
}
__device__ __forceinline__ void acc_prod(float x, float w, float& s, float& c) {
    float p = x * w;
    float pe = fmaf(x, w, -p);
    float t, e;
    twosum(s, p, t, e);
    s = t;
    c += e + pe;
}

// ---------------- prep: normalize -> fp32 xn, bf16 hi, exact xsq ----------------
__global__ void prep_kernel(const float* __restrict__ v, int rows,
                            float* __restrict__ vn,
                            __nv_bfloat16* __restrict__ hi,
                            float* __restrict__ sq) {
    int warp = (blockIdx.x * blockDim.x + threadIdx.x) >> 5;
    int lane = threadIdx.x & 31;
    if (warp >= rows) return;
    const float* row = v + (size_t)warp * DDIM;
    float vals[16];
    float s = 0.f;
#pragma unroll
    for (int i = 0; i < 16; i++) { vals[i] = row[lane + 32*i]; s = fmaf(vals[i], vals[i], s); }
#pragma unroll
    for (int o = 16; o; o >>= 1) s += __shfl_xor_sync(0xffffffffu, s, o);
    float nrm = fmaxf(sqrtf(s), EPSF);
    float s2 = 0.f, c2 = 0.f;
#pragma unroll
    for (int i = 0; i < 16; i++) {
        float xn = vals[i] / nrm;
        size_t off = (size_t)warp * DDIM + lane + 32*i;
        vn[off] = xn;
        hi[off] = __float2bfloat16(xn);
        acc_prod(xn, xn, s2, c2);
    }
#pragma unroll
    for (int o = 16; o; o >>= 1) {
        float os = __shfl_xor_sync(0xffffffffu, s2, o);
        float oc = __shfl_xor_sync(0xffffffffu, c2, o);
        float t, e;
        twosum(s2, os, t, e);
        s2 = t; c2 += oc + e;
    }
    if (lane == 0) sq[warp] = s2 + c2;
}

// ---------------- top-S insert (tie: lower index wins) ----------------
template<int S>
__device__ __forceinline__ void topk_insert(float (&d)[S], int (&ix)[S], float nd, int ni) {
#pragma unroll
    for (int s = S - 1; s >= 0; s--) {
        bool better = (nd < d[s]) || (nd == d[s] && ni < ix[s]);
        if (!better) {
#pragma unroll
            for (int t = S - 1; t > s + 1; t--) { d[t] = d[t-1]; ix[t] = ix[t-1]; }
            if (s + 1 < S) { d[s+1] = nd; ix[s+1] = ni; }
            return;
        }
    }
#pragma unroll
    for (int t = S - 1; t > 0; t--) { d[t] = d[t-1]; ix[t] = ix[t-1]; }
    d[0] = nd; ix[0] = ni;
}

// ---------------- helpers ----------------
__device__ __forceinline__ uint32_t smem_u32(const void* p) {
    uint32_t a;
    asm("{ .reg .u64 t; cvta.to.shared.u64 t, %1; cvt.u32.u64 %0, t; }" : "=r"(a) : "l"(p));
    return a;
}
__device__ __forceinline__ void cp16(void* s, const void* g) {
    unsigned sa = (unsigned)__cvta_generic_to_shared(s);
    asm volatile("cp.async.cg.shared.global [%0], [%1], 16;" :: "r"(sa), "l"(g));
}
__device__ __forceinline__ void ldsm_x4(uint32_t (&r)[4], uint32_t addr) {
    asm volatile("ldmatrix.sync.aligned.m8n8.x4.shared.b16 {%0,%1,%2,%3}, [%4];"
                 : "=r"(r[0]), "=r"(r[1]), "=r"(r[2]), "=r"(r[3]) : "r"(addr));
}

#define MMA_BF16(C, A0, A1, A2, A3, B0, B1) \
    asm volatile("mma.sync.aligned.m16n8k16.row.col.f32.bf16.bf16.f32 " \
                 "{%0,%1,%2,%3},{%4,%5,%6,%7},{%8,%9},{%0,%1,%2,%3};" \
                 : "+f"(C[0]), "+f"(C[1]), "+f"(C[2]), "+f"(C[3]) \
                 : "r"(A0), "r"(A1), "r"(A2), "r"(A3), "r"(B0), "r"(B1))

// ---------------- fused single-pass bf16 GEMM + top-8 nomination ----------------
__global__ __launch_bounds__(GEMM_THREADS, 1)
void gemm_topk_kernel() {
    extern __shared__ __align__(16) char dynsm[];
    __nv_bfloat16* sm = (__nv_bfloat16*)dynsm;
    __shared__ float wsqs[BN];

    const int tid  = threadIdx.x;
    const int warp = tid >> 5, lane = tid & 31;
    const int wm = warp >> 2, wn = warp & 3;       // 4x4 warp grid
    const int gI = lane >> 2, tig = lane & 3;
    const int row0 = blockIdx.x * BM;

    // cp.async loader mapping: 512 threads x 1 16B-chunk per piece
    const int lrow = tid >> 2;
    const int lch  = (tid & 3) * 8;   // bf16 elem offset in 32-wide k slab

    // ldmatrix address offsets (bytes), lane-dependent
    const int mat = lane >> 3, rowin = lane & 7;
    const uint32_t sm0 = smem_u32(sm);
    uint32_t offA[2][2], offB[2][2];
#pragma unroll
    for (int mt = 0; mt < 2; mt++)
#pragma unroll
        for (int k16 = 0; k16 < 2; k16++)
            offA[mt][k16] = (uint32_t)(((wm*32 + mt*16 + (mat&1)*8 + rowin)*KST
                                        + k16*16 + (mat>>1)*8) * 2);
#pragma unroll
    for (int np = 0; np < 2; np++)
#pragma unroll
        for (int k16 = 0; k16 < 2; k16++)
            offB[np][k16] = (uint32_t)(PIECE*2 + ((wn*32 + np*16 + (mat>>1)*8 + rowin)*KST
                                        + k16*16 + (mat&1)*8) * 2);

    float xsq_r[4];
#pragma unroll
    for (int s = 0; s < 4; s++)
        xsq_r[s] = g_xsq[row0 + wm*32 + (s>>1)*16 + gI + (s&1)*8];

    float td[4][3]; int ti[4][3];
#pragma unroll
    for (int s = 0; s < 4; s++) {
        td[s][0] = td[s][1] = td[s][2] = INFINITY;
        ti[s][0] = ti[s][1] = ti[s][2] = 0x7fffffff;
    }

    for (int kt = 0; kt < KCB; kt += BN) {
        if (tid < BN) wsqs[tid] = g_wsq[kt + tid];

        float acc[2][4][4];
#pragma unroll
        for (int mt = 0; mt < 2; mt++)
#pragma unroll
            for (int nt = 0; nt < 4; nt++)
#pragma unroll
                for (int j = 0; j < 4; j++) acc[mt][nt][j] = 0.f;

        // prefetch dt=0 into stage 0
        {
            __nv_bfloat16* st = sm;
            cp16(st +         lrow*KST + lch, &g_xh[(size_t)(row0+lrow)*DDIM + lch]);
            cp16(st + PIECE + lrow*KST + lch, &g_wh[(size_t)(kt  +lrow)*DDIM + lch]);
            asm volatile("cp.async.commit_group;");
        }

        for (int dt = 0; dt < DDIM/BK; dt++) {
            if (dt + 1 < DDIM/BK) {
                __nv_bfloat16* st = sm + ((dt+1)&1)*STAGE;
                int doff = (dt+1)*BK + lch;
                cp16(st +         lrow*KST + lch, &g_xh[(size_t)(row0+lrow)*DDIM + doff]);
                cp16(st + PIECE + lrow*KST + lch, &g_wh[(size_t)(kt  +lrow)*DDIM + doff]);
                asm volatile("cp.async.commit_group;");
                asm volatile("cp.async.wait_group 1;");
            } else {
                asm volatile("cp.async.wait_group 0;");
            }
            __syncthreads();

            const uint32_t stage_u32 = sm0 + (uint32_t)((dt&1)*STAGE*2);

#pragma unroll
            for (int k16 = 0; k16 < 2; k16++) {
                uint32_t a0[4], a1[4], b0[4], b1[4];
                ldsm_x4(a0, stage_u32 + offA[0][k16]);
                ldsm_x4(a1, stage_u32 + offA[1][k16]);
                ldsm_x4(b0, stage_u32 + offB[0][k16]);
                ldsm_x4(b1, stage_u32 + offB[1][k16]);

                MMA_BF16(acc[0][0], a0[0],a0[1],a0[2],a0[3], b0[0],b0[1]);
                MMA_BF16(acc[0][1], a0[0],a0[1],a0[2],a0[3], b0[2],b0[3]);
                MMA_BF16(acc[0][2], a0[0],a0[1],a0[2],a0[3], b1[0],b1[1]);
                MMA_BF16(acc[0][3], a0[0],a0[1],a0[2],a0[3], b1[2],b1[3]);
                MMA_BF16(acc[1][0], a1[0],a1[1],a1[2],a1[3], b0[0],b0[1]);
                MMA_BF16(acc[1][1], a1[0],a1[1],a1[2],a1[3], b0[2],b0[3]);
                MMA_BF16(acc[1][2], a1[0],a1[1],a1[2],a1[3], b1[0],b1[1]);
                MMA_BF16(acc[1][3], a1[0],a1[1],a1[2],a1[3], b1[2],b1[3]);
            }
            __syncthreads();
        }

        // distances + per-thread running top-3
#pragma unroll
        for (int mt = 0; mt < 2; mt++)
#pragma unroll
            for (int nt = 0; nt < 4; nt++) {
                int colb = wn*32 + nt*8 + tig*2;
                float w0 = wsqs[colb], w1 = wsqs[colb+1];
                int gc = kt + colb;
                float d00 = xsq_r[mt*2]   + w0 - 2.f*acc[mt][nt][0];
                float d01 = xsq_r[mt*2]   + w1 - 2.f*acc[mt][nt][1];
                float d10 = xsq_r[mt*2+1] + w0 - 2.f*acc[mt][nt][2];
                float d11 = xsq_r[mt*2+1] + w1 - 2.f*acc[mt][nt][3];
                topk_insert<3>(td[mt*2],   ti[mt*2],   d00, gc);
                topk_insert<3>(td[mt*2],   ti[mt*2],   d01, gc+1);
                topk_insert<3>(td[mt*2+1], ti[mt*2+1], d10, gc);
                topk_insert<3>(td[mt*2+1], ti[mt*2+1], d11, gc+1);
            }
        __syncthreads();
    }

    // cross-thread reduce: 16 owner threads per row, 48 candidates -> top-8
    float* cd = (float*)dynsm;                          // [BM][48]
    int*   ci = (int*)(dynsm + BM*48*sizeof(float));    // [BM][48]
#pragma unroll
    for (int s = 0; s < 4; s++) {
        int rl = wm*32 + (s>>1)*16 + gI + (s&1)*8;
        int cs = (wn*4 + tig)*3;
#pragma unroll
        for (int j = 0; j < 3; j++) {
            cd[rl*48 + cs + j] = td[s][j];
            ci[rl*48 + cs + j] = ti[s][j];
        }
    }
    __syncthreads();

    if (tid < BM) {
        float bd[8]; int bi[8];
#pragma unroll
        for (int s = 0; s < 8; s++) { bd[s] = INFINITY; bi[s] = 0x7fffffff; }
        for (int c = 0; c < 48; c++)
            topk_insert<8>(bd, bi, cd[tid*48 + c], ci[tid*48 + c]);
        int r = row0 + tid;
#pragma unroll
        for (int s = 0; s < 8; s++) g_top8[r*8 + s] = bi[s];
    }
}

// ---------------- epilogue: exact refine (warp per candidate), weights, quantize, loss ----------------
__global__ __launch_bounds__(256)
void epilogue_kernel(const float* __restrict__ x, const float* __restrict__ emb,
                     float* __restrict__ out) {
    const int n = blockIdx.x;
    const int t = threadIdx.x;     // 256 threads
    const int w = t >> 5, lane = t & 31;
    __shared__ int   cidx[8];
    __shared__ float dist8[8];
    __shared__ float ws[3];
    __shared__ int   sel[3];
    __shared__ float red[256];

    if (t < 8) cidx[t] = g_top8[n*8 + t];
    __syncthreads();

    // warp w: compensated-exact dot(xn, wn[cidx[w]])
    {
        const float* xr = g_xn + (size_t)n * DDIM;
        const float* wr = g_wn + (size_t)cidx[w] * DDIM;
        float s = 0.f, c = 0.f;
#pragma unroll
        for (int i = 0; i < 16; i++)
            acc_prod(xr[lane + 32*i], wr[lane + 32*i], s, c);
#pragma unroll
        for (int o = 16; o; o >>= 1) {
            float os = __shfl_xor_sync(0xffffffffu, s, o);
            float oc = __shfl_xor_sync(0xffffffffu, c, o);
            float tt, e;
            twosum(s, os, tt, e);
            s = tt; c += oc + e;
        }
        if (lane == 0)
            dist8[w] = g_xsq[n] + g_wsq[cidx[w]] - 2.f * (s + c);
    }
    __syncthreads();

    if (t == 0) {
        float bd[3] = {INFINITY, INFINITY, INFINITY};
        int   bs[3] = {0, 0, 0};
        bool  hv[3] = {false, false, false};
        for (int c = 0; c < 8; c++) {
            float nd = dist8[c]; int ni = cidx[c];
            if (!hv[2] || nd < bd[2] || (nd == bd[2] && ni < cidx[bs[2]])) {
                if (!hv[1] || nd < bd[1] || (nd == bd[1] && ni < cidx[bs[1]])) {
                    bd[2] = bd[1]; bs[2] = bs[1]; hv[2] = hv[1];
                    if (!hv[0] || nd < bd[0] || (nd == bd[0] && ni < cidx[bs[0]])) {
                        bd[1] = bd[0]; bs[1] = bs[0]; hv[1] = hv[0];
                        bd[0] = nd;   bs[0] = c;     hv[0] = true;
                    } else { bd[1] = nd; bs[1] = c; hv[1] = true; }
                } else { bd[2] = nd; bs[2] = c; hv[2] = true; }
            }
        }
        float v0 = 1.f/bd[0], v1 = 1.f/bd[1], v2 = 1.f/bd[2];
        float ssum = (v0 + v1) + v2;
        ws[0] = v0/ssum; ws[1] = v1/ssum; ws[2] = v2/ssum;
        sel[0] = cidx[bs[0]]; sel[1] = cidx[bs[1]]; sel[2] = cidx[bs[2]];
        float* idx_out = out + (size_t)NROWS*DDIM + 1;
        idx_out[n*3+0] = (float)sel[0];
        idx_out[n*3+1] = (float)sel[1];
        idx_out[n*3+2] = (float)sel[2];
    }
    __syncthreads();

    const float w0 = ws[0], w1 = ws[1], w2 = ws[2];
    const float* e0 = emb + (size_t)sel[0]*DDIM;
    const float* e1 = emb + (size_t)sel[1]*DDIM;
    const float* e2 = emb + (size_t)sel[2]*DDIM;

    float local = 0.f;
#pragma unroll
    for (int d = t; d < DDIM; d += 256) {
        float q  = fmaf(w2, e2[d], fmaf(w1, e1[d], w0*e0[d]));
        float xv = x[(size_t)n*DDIM + d];
        float diff = q - xv;
        out[(size_t)n*DDIM + d] = xv + diff;
        local = fmaf(diff, diff, local);
    }
    red[t] = local;
    __syncthreads();
#pragma unroll
    for (int o = 128; o; o >>= 1) {
        if (t < o) red[t] += red[t+o];
        __syncthreads();
    }
    if (t == 0) g_rowsum[n] = red[0];
}

// ---------------- deterministic loss reduction ----------------
__global__ void loss_kernel(float* __restrict__ out) {
    __shared__ double red[256];
    int t = threadIdx.x;
    double s = 0.0;
    for (int i = t; i < NROWS; i += 256) s += (double)g_rowsum[i];
    red[t] = s;
    __syncthreads();
#pragma unroll
    for (int o = 128; o; o >>= 1) {
        if (t < o) red[t] += red[t+o];
        __syncthreads();
    }
    if (t == 0) {
        double mean = red[0] / (double)((size_t)NROWS*DDIM);
        out[(size_t)NROWS*DDIM] = (float)(1.25 * mean);
    }
}

// ---------------- launch ----------------
extern "C" void kernel_launch(void* const* d_in, const int* in_sizes, int n_in,
                              void* d_out, int out_size) {
    const float* x   = (const float*)d_in[0];
    const float* emb = (const float*)d_in[1];
    float* out = (float*)d_out;

    __nv_bfloat16 *p_xh, *p_wh;
    float *p_xn, *p_wn, *p_xsq, *p_wsq;
    cudaGetSymbolAddress((void**)&p_xh,  g_xh);
    cudaGetSymbolAddress((void**)&p_wh,  g_wh);
    cudaGetSymbolAddress((void**)&p_xn,  g_xn);
    cudaGetSymbolAddress((void**)&p_wn,  g_wn);
    cudaGetSymbolAddress((void**)&p_xsq, g_xsq);
    cudaGetSymbolAddress((void**)&p_wsq, g_wsq);

    cudaFuncSetAttribute(gemm_topk_kernel,
                         cudaFuncAttributeMaxDynamicSharedMemorySize, SMEM_BYTES);

    prep_kernel<<<KCB/8,   256>>>(emb, KCB,   p_wn, p_wh, p_wsq);
    prep_kernel<<<NROWS/8, 256>>>(x,   NROWS, p_xn, p_xh, p_xsq);
    gemm_topk_kernel<<<NROWS/BM, GEMM_THREADS, SMEM_BYTES>>>();
    epilogue_kernel<<<NROWS, 256>>>(x, emb, out);
    loss_kernel<<<1, 256>>>(out);
}